// round 13
// baseline (speedup 1.0000x reference)
#include <cuda_runtime.h>
#include <cuda_fp16.h>
#include <math.h>
#include <stdint.h>

// ---------------------------------------------------------------------------
// FeatureMixer, all-fp16 mma.sync.m16n8k16 (fp32 accum), fp32 LN/gelu.
//   params = qf @ W_gen + b_gen        (3600 x 24576, K=256)    fp16 HMMA
//   per (row,h): channel mix+gelu+LN2d, spatial mix+gelu+LN2d   fp16 HMMA
//   out    = mid @ W_out, +b, LN(256)  (3600 x 256, K=16384)    fp16 HMMA splitK
// R12: GEMM CTA tile 128x256, warp tile 64x64 (2x4 grid) -> 33% fewer
//      LDSM per MMA, 31% less L1 traffic (gemm1 was L1-bound at 61%).
// ---------------------------------------------------------------------------

#define DEV __device__ __forceinline__

constexpr int MROWS = 3600;
constexpr int N1    = 24576;
constexpr int K1    = 256;
constexpr int NMID  = 16384;
constexpr int NOUT  = 256;
constexpr int SPLITK = 16;

constexpr int STAGE_BYTES = 30720;           // A 10240 + B 20480
constexpr int SMEM_BYTES  = 3 * STAGE_BYTES; // 92160

__device__ __align__(128) __half g_qf_h[(size_t)MROWS * K1];
__device__ __align__(128) __half g_wgenT_h[(size_t)N1 * K1];
__device__ __align__(128) __half g_woutT_h[(size_t)NOUT * NMID];
__device__ __align__(128) __half g_params_h[(size_t)MROWS * N1];
__device__ __align__(128) __half g_mid_h[(size_t)MROWS * NMID];
__device__ __align__(128) float  g_part[(size_t)SPLITK * MROWS * NOUT];

// ---------------------------------------------------------------------------
DEV uint32_t smem_u32(const void* p) {
    uint32_t a;
    asm("{ .reg .u64 t; cvta.to.shared.u64 t, %1; cvt.u32.u64 %0, t; }"
        : "=r"(a) : "l"(p));
    return a;
}

DEV void mma16(float* c, const uint32_t* a, const uint32_t* b) {
    asm volatile(
        "mma.sync.aligned.m16n8k16.row.col.f32.f16.f16.f32 "
        "{%0,%1,%2,%3}, {%4,%5,%6,%7}, {%8,%9}, {%0,%1,%2,%3};\n"
        : "+f"(c[0]), "+f"(c[1]), "+f"(c[2]), "+f"(c[3])
        : "r"(a[0]), "r"(a[1]), "r"(a[2]), "r"(a[3]), "r"(b[0]), "r"(b[1]));
}

DEV void ldsm4(uint32_t& r0, uint32_t& r1, uint32_t& r2, uint32_t& r3,
               uint32_t addr) {
    asm volatile(
        "ldmatrix.sync.aligned.m8n8.x4.shared.b16 {%0,%1,%2,%3}, [%4];"
        : "=r"(r0), "=r"(r1), "=r"(r2), "=r"(r3) : "r"(addr));
}

DEV void cp16(uint32_t dst, const void* src, int sz) {
    asm volatile("cp.async.cg.shared.global [%0], [%1], 16, %2;\n"
                 :: "r"(dst), "l"(src), "r"(sz));
}
DEV void cp_commit() { asm volatile("cp.async.commit_group;\n" ::: "memory"); }
DEV void cp_wait1()  { asm volatile("cp.async.wait_group 1;\n" ::: "memory"); }

DEV float gelu_exact(float x) {
    return 0.5f * x * (1.0f + erff(x * 0.70710678118654752f));
}

// block-wide (256 thr) sum + sumsq
DEV void block_reduce2(float& s, float& ss, float* red, int tid) {
#pragma unroll
    for (int o = 16; o > 0; o >>= 1) {
        s  += __shfl_xor_sync(0xffffffffu, s, o);
        ss += __shfl_xor_sync(0xffffffffu, ss, o);
    }
    if ((tid & 31) == 0) { red[tid >> 5] = s; red[8 + (tid >> 5)] = ss; }
    __syncthreads();
    s = 0.f; ss = 0.f;
#pragma unroll
    for (int i = 0; i < 8; ++i) { s += red[i]; ss += red[8 + i]; }
}

// group-wide (128 thr = 4 warps) sum + sumsq with a named barrier.
DEV void group_reduce2(float& s, float& ss, float* red, int warp4, int lane,
                       int barid) {
#pragma unroll
    for (int o = 16; o > 0; o >>= 1) {
        s  += __shfl_xor_sync(0xffffffffu, s, o);
        ss += __shfl_xor_sync(0xffffffffu, ss, o);
    }
    if (lane == 0) { red[warp4] = s; red[4 + warp4] = ss; }
    asm volatile("bar.sync %0, 128;" :: "r"(barid) : "memory");
    s  = red[0] + red[1] + red[2] + red[3];
    ss = red[4] + red[5] + red[6] + red[7];
}

DEV void group_bar(int barid) {
    asm volatile("bar.sync %0, 128;" :: "r"(barid) : "memory");
}

// permutation of param-gen columns: p1 block (n<16384): (h,c,d) -> (h,d,c)
// involution: permn(permn(n)) == n
DEV int permn(int n) {
    if (n < 16384) {
        int h = n >> 12, rem = n & 4095, c = rem >> 6, d = rem & 63;
        return (h << 12) + (d << 6) + c;
    }
    return n;
}

// ---------------------------------------------------------------------------
// fp16 GEMM mainloop: CTA tile 128x256, BK=32, 3-stage cp.async pipeline.
// 8 warps as 2x4 grid, warp tile 64x64. smem stage: A 128x80B + B 256x80B.
// ---------------------------------------------------------------------------
DEV void stage_load(uint32_t sbase,
                    const __half* __restrict__ A, int lda, int mBase,
                    const __half* __restrict__ Bt, int ldb, int nBase,
                    int k0, int t) {
#pragma unroll
    for (int j = 0; j < 2; ++j) {          // A: 128 rows x 4 chunks
        int i = t + j * 256, r = i >> 2, c = i & 3;
        int gr = mBase + r;
        const __half* sa = A + (size_t)(gr < MROWS ? gr : 0) * lda + k0 + c * 8;
        cp16(sbase + (uint32_t)(r * 80 + c * 16), sa, gr < MROWS ? 16 : 0);
    }
#pragma unroll
    for (int j = 0; j < 4; ++j) {          // B: 256 rows x 4 chunks
        int i = t + j * 256, r = i >> 2, c = i & 3;
        const __half* sb = Bt + (size_t)(nBase + r) * ldb + k0 + c * 8;
        cp16(sbase + 10240u + (uint32_t)(r * 80 + c * 16), sb, 16);
    }
}

template <int NT>
DEV void mainloop_h(const __half* __restrict__ A, int lda, int mBase,
                    const __half* __restrict__ Bt, int ldb, int nBase,
                    int kStart, uint32_t sm32, float (&acc)[4][8][4], int t) {
    const int lane = t & 31, warp = t >> 5;
    const int wr = warp >> 2, wc = warp & 3;
    const int sub = lane & 7;

    const int aRow = ((lane >> 3) & 1) * 8 + sub;
    const int aK   = (lane >> 4) * 8;
    const int bRow = (lane >> 4) * 8 + sub;
    const int bK   = ((lane >> 3) & 1) * 8;

    stage_load(sm32, A, lda, mBase, Bt, ldb, nBase, kStart, t);
    cp_commit();
    stage_load(sm32 + STAGE_BYTES, A, lda, mBase, Bt, ldb, nBase, kStart + 32, t);
    cp_commit();

    for (int kt = 0; kt < NT; ++kt) {
        cp_wait1();
        __syncthreads();

        const uint32_t aB = sm32 + (uint32_t)((kt % 3) * STAGE_BYTES);
        const uint32_t bB = aB + 10240u;

#pragma unroll
        for (int kk = 0; kk < 32; kk += 16) {
            uint32_t af[4][4], bf[8][2];
#pragma unroll
            for (int mi = 0; mi < 4; ++mi) {
                int r = wr * 64 + mi * 16 + aRow;
                ldsm4(af[mi][0], af[mi][1], af[mi][2], af[mi][3],
                      aB + (uint32_t)(r * 80 + (kk + aK) * 2));
            }
#pragma unroll
            for (int n2 = 0; n2 < 4; ++n2) {
                int n = wc * 64 + n2 * 16 + bRow;
                ldsm4(bf[n2 * 2][0], bf[n2 * 2][1], bf[n2 * 2 + 1][0],
                      bf[n2 * 2 + 1][1],
                      bB + (uint32_t)(n * 80 + (kk + bK) * 2));
            }
#pragma unroll
            for (int mi = 0; mi < 4; ++mi)
#pragma unroll
                for (int ni = 0; ni < 8; ++ni) mma16(acc[mi][ni], af[mi], bf[ni]);
        }

        if (kt + 2 < NT)
            stage_load(sm32 + (uint32_t)(((kt + 2) % 3) * STAGE_BYTES),
                       A, lda, mBase, Bt, ldb, nBase, kStart + (kt + 2) * 32, t);
        cp_commit();
    }
}

// ---------------------------------------------------------------------------
// GEMM1: g_params_h = qf_h @ wgenT_h^T + b_gen[permn(.)]   grid(96,29)
// ---------------------------------------------------------------------------
__global__ void __launch_bounds__(256, 1)
gemm1_h_kernel(const float* __restrict__ b_gen) {
    extern __shared__ __align__(128) __half smem_dyn[];
    const int t = threadIdx.x, lane = t & 31, warp = t >> 5;
    const int g = lane >> 2, tg = lane & 3;
    const int wr = warp >> 2, wc = warp & 3;
    const int mBase = blockIdx.y * 128, nBase = blockIdx.x * 256;

    float acc[4][8][4];
#pragma unroll
    for (int i = 0; i < 4; ++i)
#pragma unroll
        for (int j = 0; j < 8; ++j)
#pragma unroll
            for (int k = 0; k < 4; ++k) acc[i][j][k] = 0.f;

    mainloop_h<8>(g_qf_h, K1, mBase, g_wgenT_h, K1, nBase, 0,
                  smem_u32(smem_dyn), acc, t);

#pragma unroll
    for (int mi = 0; mi < 4; ++mi) {
        int r0 = mBase + wr * 64 + mi * 16 + g;
#pragma unroll
        for (int ni = 0; ni < 8; ++ni) {
            int c0 = nBase + wc * 64 + ni * 8 + tg * 2;
            float b0 = b_gen[permn(c0)], b1 = b_gen[permn(c0 + 1)];
            if (r0 < MROWS)
                *(__half2*)(g_params_h + (size_t)r0 * N1 + c0) =
                    __floats2half2_rn(acc[mi][ni][0] + b0, acc[mi][ni][1] + b1);
            if (r0 + 8 < MROWS)
                *(__half2*)(g_params_h + (size_t)(r0 + 8) * N1 + c0) =
                    __floats2half2_rn(acc[mi][ni][2] + b0, acc[mi][ni][3] + b1);
        }
    }
}

// ---------------------------------------------------------------------------
// GEMM3: g_part[z] = g_mid_h @ woutT_h^T    grid(1,29,16)
// ---------------------------------------------------------------------------
__global__ void __launch_bounds__(256, 1)
gemm3_h_kernel() {
    extern __shared__ __align__(128) __half smem_dyn[];
    const int t = threadIdx.x, lane = t & 31, warp = t >> 5;
    const int g = lane >> 2, tg = lane & 3;
    const int wr = warp >> 2, wc = warp & 3;
    const int mBase = blockIdx.y * 128, nBase = 0;
    const int kStart = blockIdx.z * (NMID / SPLITK);

    float acc[4][8][4];
#pragma unroll
    for (int i = 0; i < 4; ++i)
#pragma unroll
        for (int j = 0; j < 8; ++j)
#pragma unroll
            for (int k = 0; k < 4; ++k) acc[i][j][k] = 0.f;

    mainloop_h<(NMID / SPLITK) / 32>(g_mid_h, NMID, mBase, g_woutT_h, NMID,
                                     nBase, kStart, smem_u32(smem_dyn), acc, t);

    float* pbase = g_part + (size_t)blockIdx.z * MROWS * NOUT;
#pragma unroll
    for (int mi = 0; mi < 4; ++mi) {
        int r0 = mBase + wr * 64 + mi * 16 + g;
#pragma unroll
        for (int ni = 0; ni < 8; ++ni) {
            int c0 = wc * 64 + ni * 8 + tg * 2;
            if (r0 < MROWS) {
                pbase[(size_t)r0 * NOUT + c0]     = acc[mi][ni][0];
                pbase[(size_t)r0 * NOUT + c0 + 1] = acc[mi][ni][1];
            }
            if (r0 + 8 < MROWS) {
                pbase[(size_t)(r0 + 8) * NOUT + c0]     = acc[mi][ni][2];
                pbase[(size_t)(r0 + 8) * NOUT + c0 + 1] = acc[mi][ni][3];
            }
        }
    }
}

// ---------------------------------------------------------------------------
// Mid kernel (fp16 HMMA): one CTA per (b,q) row; two independent 128-thread
// head-groups (warps 0-3: heads 0,2; warps 4-7: heads 1,3), named barriers.
// ---------------------------------------------------------------------------
__global__ void __launch_bounds__(256, 3)
mid_h_kernel(const float* __restrict__ sampled) {
    __shared__ __align__(16) __half sP1[2][64 * 72];  // [d][c]
    __shared__ __align__(16) __half sS[2][32 * 72];   // [p][c]
    __shared__ __align__(16) __half sP2[2][64 * 40];  // [e][p]
    __shared__ __align__(16) __half sO1[2][64 * 40];  // [d][p]
    __shared__ float red[2][8];

    const int row = blockIdx.x, t = threadIdx.x;
    const int lane = t & 31;
    const int wg = t >> 7;            // head-group 0/1
    const int wt = t & 127;           // thread-in-group
    const int warp4 = wt >> 5;        // warp-in-group 0-3
    const int g = lane >> 2, tg = lane & 3;
    const int barid = wg + 1;

    const __half* prow = g_params_h + (size_t)row * N1;
    const float* srow = sampled + (size_t)row * 8192;
    __half* mrow = g_mid_h + (size_t)row * NMID;

    __half* P1 = sP1[wg];
    __half* S  = sS[wg];
    __half* P2 = sP2[wg];
    __half* O1 = sO1[wg];
    float*  rd = red[wg];

    const int mA = (warp4 & 1) * 16;
    const int nA = (warp4 >> 1) * 32;
    const int mB = (warp4 & 1) * 32;
    const int nB = (warp4 >> 1) * 32;

    for (int h2 = 0; h2 < 2; ++h2) {
        const int head = h2 * 2 + wg;
        group_bar(barid);

#pragma unroll
        for (int j = 0; j < 4; ++j) {
            int i = wt + j * 128, d = i >> 3, c8 = i & 7;
            *(uint4*)(P1 + d * 72 + c8 * 8) =
                *(const uint4*)(prow + head * 4096 + d * 64 + c8 * 8);
        }
#pragma unroll
        for (int j = 0; j < 4; ++j) {
            int i = wt + j * 128, p = i >> 4, c4 = i & 15;
            float4 v = *(const float4*)(srow + head * 2048 + p * 64 + c4 * 4);
            __half2 ha = __floats2half2_rn(v.x, v.y);
            __half2 hb = __floats2half2_rn(v.z, v.w);
            *(uint2*)(S + p * 72 + c4 * 4) =
                make_uint2(*(uint32_t*)&ha, *(uint32_t*)&hb);
        }
#pragma unroll
        for (int j = 0; j < 2; ++j) {
            int i = wt + j * 128, e = i >> 2, p8 = i & 3;
            *(uint4*)(P2 + e * 40 + p8 * 8) =
                *(const uint4*)(prow + 16384 + head * 2048 + e * 32 + p8 * 8);
        }
        group_bar(barid);

        // ---- stage A: M=32(p) N=64(d) K=64(c), warp tile 16x32 ----
        float accA[4][4];
#pragma unroll
        for (int i = 0; i < 4; ++i)
#pragma unroll
            for (int j = 0; j < 4; ++j) accA[i][j] = 0.f;

        const int p0 = mA + g;
#pragma unroll
        for (int kk = 0; kk < 64; kk += 16) {
            uint32_t a[4];
            a[0] = *(const uint32_t*)(S + p0 * 72 + kk + 2 * tg);
            a[1] = *(const uint32_t*)(S + (p0 + 8) * 72 + kk + 2 * tg);
            a[2] = *(const uint32_t*)(S + p0 * 72 + kk + 2 * tg + 8);
            a[3] = *(const uint32_t*)(S + (p0 + 8) * 72 + kk + 2 * tg + 8);
#pragma unroll
            for (int ni = 0; ni < 4; ++ni) {
                int nd = nA + ni * 8 + g;
                uint32_t b[2];
                b[0] = *(const uint32_t*)(P1 + nd * 72 + kk + 2 * tg);
                b[1] = *(const uint32_t*)(P1 + nd * 72 + kk + 2 * tg + 8);
                mma16(accA[ni], a, b);
            }
        }

        float s = 0.f, ss = 0.f;
#pragma unroll
        for (int i = 0; i < 4; ++i)
#pragma unroll
            for (int j = 0; j < 4; ++j) {
                accA[i][j] = gelu_exact(accA[i][j]);
                s += accA[i][j]; ss += accA[i][j] * accA[i][j];
            }
        group_reduce2(s, ss, rd, warp4, lane, barid);
        float mean = s * (1.f / 2048.f);
        float inv  = rsqrtf(ss * (1.f / 2048.f) - mean * mean + 1e-5f);
#pragma unroll
        for (int ni = 0; ni < 4; ++ni) {
            int d0 = nA + ni * 8 + 2 * tg;
            O1[d0 * 40 + p0]           = __float2half_rn((accA[ni][0] - mean) * inv);
            O1[(d0 + 1) * 40 + p0]     = __float2half_rn((accA[ni][1] - mean) * inv);
            O1[d0 * 40 + p0 + 8]       = __float2half_rn((accA[ni][2] - mean) * inv);
            O1[(d0 + 1) * 40 + p0 + 8] = __float2half_rn((accA[ni][3] - mean) * inv);
        }
        group_bar(barid);

        // ---- stage B: M=64(e) N=64(d) K=32(p), warp tile 32x32 ----
        float accB[2][4][4];
#pragma unroll
        for (int i = 0; i < 2; ++i)
#pragma unroll
            for (int j = 0; j < 4; ++j)
#pragma unroll
                for (int k = 0; k < 4; ++k) accB[i][j][k] = 0.f;

#pragma unroll
        for (int kk = 0; kk < 32; kk += 16) {
            uint32_t a[2][4];
#pragma unroll
            for (int mi = 0; mi < 2; ++mi) {
                int e0 = mB + mi * 16 + g;
                a[mi][0] = *(const uint32_t*)(P2 + e0 * 40 + kk + 2 * tg);
                a[mi][1] = *(const uint32_t*)(P2 + (e0 + 8) * 40 + kk + 2 * tg);
                a[mi][2] = *(const uint32_t*)(P2 + e0 * 40 + kk + 2 * tg + 8);
                a[mi][3] = *(const uint32_t*)(P2 + (e0 + 8) * 40 + kk + 2 * tg + 8);
            }
#pragma unroll
            for (int ni = 0; ni < 4; ++ni) {
                int nd = nB + ni * 8 + g;
                uint32_t b[2];
                b[0] = *(const uint32_t*)(O1 + nd * 40 + kk + 2 * tg);
                b[1] = *(const uint32_t*)(O1 + nd * 40 + kk + 2 * tg + 8);
#pragma unroll
                for (int mi = 0; mi < 2; ++mi) mma16(accB[mi][ni], a[mi], b);
            }
        }

        s = 0.f; ss = 0.f;
#pragma unroll
        for (int i = 0; i < 2; ++i)
#pragma unroll
            for (int j = 0; j < 4; ++j)
#pragma unroll
                for (int k = 0; k < 4; ++k) {
                    accB[i][j][k] = gelu_exact(accB[i][j][k]);
                    s += accB[i][j][k]; ss += accB[i][j][k] * accB[i][j][k];
                }
        group_reduce2(s, ss, rd, warp4, lane, barid);
        mean = s * (1.f / 4096.f);
        inv  = rsqrtf(ss * (1.f / 4096.f) - mean * mean + 1e-5f);
        __half* hrow = mrow + head * 4096;
#pragma unroll
        for (int mi = 0; mi < 2; ++mi) {
            int e0 = mB + mi * 16 + g;
#pragma unroll
            for (int ni = 0; ni < 4; ++ni) {
                int c0 = nB + ni * 8 + 2 * tg;
                *(__half2*)(hrow + e0 * 64 + c0) =
                    __floats2half2_rn((accB[mi][ni][0] - mean) * inv,
                                      (accB[mi][ni][1] - mean) * inv);
                *(__half2*)(hrow + (e0 + 8) * 64 + c0) =
                    __floats2half2_rn((accB[mi][ni][2] - mean) * inv,
                                      (accB[mi][ni][3] - mean) * inv);
            }
        }
    }
}

// ---------------------------------------------------------------------------
// conversions
// ---------------------------------------------------------------------------
__global__ void __launch_bounds__(256)
cvt_qf_kernel(const float* __restrict__ in) {
    int i = blockIdx.x * 256 + threadIdx.x;
    float4 v = *(const float4*)(in + (size_t)i * 4);
    __half2 ha = __floats2half2_rn(v.x, v.y);
    __half2 hb = __floats2half2_rn(v.z, v.w);
    *(uint2*)(g_qf_h + (size_t)i * 4) = make_uint2(*(uint32_t*)&ha, *(uint32_t*)&hb);
}

__global__ void __launch_bounds__(256)
cvt_wgen_kernel(const float* __restrict__ in) {
    __shared__ float tile[32][33];
    const int n0 = blockIdx.x * 32, k0 = blockIdx.y * 32;
    const int tx = threadIdx.x, ty = threadIdx.y;
#pragma unroll
    for (int j = 0; j < 32; j += 8)
        tile[ty + j][tx] = in[(size_t)(k0 + ty + j) * N1 + n0 + tx];
    __syncthreads();
#pragma unroll
    for (int j = 0; j < 32; j += 8) {
        int np = permn(n0 + ty + j);
        g_wgenT_h[(size_t)np * K1 + k0 + tx] = __float2half_rn(tile[tx][ty + j]);
    }
}

__global__ void __launch_bounds__(256)
cvt_wout_kernel(const float* __restrict__ in) {
    __shared__ float tile[32][33];
    const int n0 = blockIdx.x * 32, k0 = blockIdx.y * 32;
    const int tx = threadIdx.x, ty = threadIdx.y;
#pragma unroll
    for (int j = 0; j < 32; j += 8)
        tile[ty + j][tx] = in[(size_t)(k0 + ty + j) * NOUT + n0 + tx];
    __syncthreads();
#pragma unroll
    for (int j = 0; j < 32; j += 8)
        g_woutT_h[(size_t)(n0 + ty + j) * NMID + k0 + tx] = __float2half_rn(tile[tx][ty + j]);
}

// ---------------------------------------------------------------------------
// Epilogue: deterministic split-K reduce + bias + affine LayerNorm(256)
// ---------------------------------------------------------------------------
__global__ void __launch_bounds__(256, 1)
out_ln_kernel(const float* __restrict__ b_out, const float* __restrict__ ln_w,
              const float* __restrict__ ln_b, float* __restrict__ out) {
    __shared__ float red[16];
    const int row = blockIdx.x, t = threadIdx.x;
    float v = b_out[t];
#pragma unroll
    for (int sp = 0; sp < SPLITK; ++sp)
        v += g_part[(size_t)sp * MROWS * NOUT + (size_t)row * NOUT + t];
    float s = v, ss = v * v;
    block_reduce2(s, ss, red, t);
    float mean = s * (1.f / 256.f);
    float inv  = rsqrtf(ss * (1.f / 256.f) - mean * mean + 1e-5f);
    out[(size_t)row * NOUT + t] = (v - mean) * inv * ln_w[t] + ln_b[t];
}

// ---------------------------------------------------------------------------
extern "C" void kernel_launch(void* const* d_in, const int* in_sizes, int n_in,
                              void* d_out, int out_size) {
    (void)in_sizes; (void)n_in; (void)out_size;
    const float* qf      = (const float*)d_in[0];
    const float* sampled = (const float*)d_in[1];
    const float* W_gen   = (const float*)d_in[2];
    const float* b_gen   = (const float*)d_in[3];
    const float* W_out   = (const float*)d_in[4];
    const float* b_out   = (const float*)d_in[5];
    const float* ln_w    = (const float*)d_in[6];
    const float* ln_b    = (const float*)d_in[7];

    cudaFuncSetAttribute(gemm1_h_kernel,
                         cudaFuncAttributeMaxDynamicSharedMemorySize, SMEM_BYTES);
    cudaFuncSetAttribute(gemm3_h_kernel,
                         cudaFuncAttributeMaxDynamicSharedMemorySize, SMEM_BYTES);

    cvt_qf_kernel<<<(MROWS * K1 / 4) / 256, 256>>>(qf);
    cvt_wgen_kernel<<<dim3(N1 / 32, K1 / 32), dim3(32, 8)>>>(W_gen);
    cvt_wout_kernel<<<dim3(NOUT / 32, NMID / 32), dim3(32, 8)>>>(W_out);

    gemm1_h_kernel<<<dim3(N1 / 256, (MROWS + 127) / 128), 256, SMEM_BYTES>>>(b_gen);
    mid_h_kernel<<<MROWS, 256>>>(sampled);
    gemm3_h_kernel<<<dim3(1, (MROWS + 127) / 128, SPLITK), 256, SMEM_BYTES>>>();
    out_ln_kernel<<<MROWS, 256>>>(b_out, ln_w, ln_b, (float*)d_out);
}

// round 15
// speedup vs baseline: 1.0979x; 1.0979x over previous
#include <cuda_runtime.h>
#include <cuda_fp16.h>
#include <math.h>
#include <stdint.h>

// ---------------------------------------------------------------------------
// FeatureMixer, all-fp16 mma.sync.m16n8k16 (fp32 accum), fp32 LN/gelu.
//   params = qf @ W_gen + b_gen        (3600 x 24576, K=256)    fp16 HMMA
//   per (row,h): channel mix+gelu+LN2d, spatial mix+gelu+LN2d   fp16 HMMA
//   out    = mid @ W_out, +b, LN(256)  (3600 x 256, K=16384)    fp16 HMMA splitK
// R14b (resubmit; R14 hit a container infra failure): R11 GEMM tiles
//      (128x128, warp 64x32, 2 CTAs/SM) + 4-stage cp.async pipeline
//      (prefetch distance 3) to close the remaining latency exposure.
// ---------------------------------------------------------------------------

#define DEV __device__ __forceinline__

constexpr int MROWS = 3600;
constexpr int N1    = 24576;
constexpr int K1    = 256;
constexpr int NMID  = 16384;
constexpr int NOUT  = 256;
constexpr int SPLITK = 16;

constexpr int STAGE_BYTES = 20480;           // A 10240 + B 10240
constexpr int STAGES      = 4;
constexpr int SMEM_BYTES  = STAGES * STAGE_BYTES; // 81920

__device__ __align__(128) __half g_qf_h[(size_t)MROWS * K1];
__device__ __align__(128) __half g_wgenT_h[(size_t)N1 * K1];
__device__ __align__(128) __half g_woutT_h[(size_t)NOUT * NMID];
__device__ __align__(128) __half g_params_h[(size_t)MROWS * N1];
__device__ __align__(128) __half g_mid_h[(size_t)MROWS * NMID];
__device__ __align__(128) float  g_part[(size_t)SPLITK * MROWS * NOUT];

// ---------------------------------------------------------------------------
DEV uint32_t smem_u32(const void* p) {
    uint32_t a;
    asm("{ .reg .u64 t; cvta.to.shared.u64 t, %1; cvt.u32.u64 %0, t; }"
        : "=r"(a) : "l"(p));
    return a;
}

DEV void mma16(float* c, const uint32_t* a, const uint32_t* b) {
    asm volatile(
        "mma.sync.aligned.m16n8k16.row.col.f32.f16.f16.f32 "
        "{%0,%1,%2,%3}, {%4,%5,%6,%7}, {%8,%9}, {%0,%1,%2,%3};\n"
        : "+f"(c[0]), "+f"(c[1]), "+f"(c[2]), "+f"(c[3])
        : "r"(a[0]), "r"(a[1]), "r"(a[2]), "r"(a[3]), "r"(b[0]), "r"(b[1]));
}

DEV void ldsm4(uint32_t& r0, uint32_t& r1, uint32_t& r2, uint32_t& r3,
               uint32_t addr) {
    asm volatile(
        "ldmatrix.sync.aligned.m8n8.x4.shared.b16 {%0,%1,%2,%3}, [%4];"
        : "=r"(r0), "=r"(r1), "=r"(r2), "=r"(r3) : "r"(addr));
}

DEV void cp16(uint32_t dst, const void* src, int sz) {
    asm volatile("cp.async.cg.shared.global [%0], [%1], 16, %2;\n"
                 :: "r"(dst), "l"(src), "r"(sz));
}
DEV void cp_commit() { asm volatile("cp.async.commit_group;\n" ::: "memory"); }
DEV void cp_wait2()  { asm volatile("cp.async.wait_group 2;\n" ::: "memory"); }

DEV float gelu_exact(float x) {
    return 0.5f * x * (1.0f + erff(x * 0.70710678118654752f));
}

// block-wide (256 thr) sum + sumsq
DEV void block_reduce2(float& s, float& ss, float* red, int tid) {
#pragma unroll
    for (int o = 16; o > 0; o >>= 1) {
        s  += __shfl_xor_sync(0xffffffffu, s, o);
        ss += __shfl_xor_sync(0xffffffffu, ss, o);
    }
    if ((tid & 31) == 0) { red[tid >> 5] = s; red[8 + (tid >> 5)] = ss; }
    __syncthreads();
    s = 0.f; ss = 0.f;
#pragma unroll
    for (int i = 0; i < 8; ++i) { s += red[i]; ss += red[8 + i]; }
}

// group-wide (128 thr = 4 warps) sum + sumsq with a named barrier.
DEV void group_reduce2(float& s, float& ss, float* red, int warp4, int lane,
                       int barid) {
#pragma unroll
    for (int o = 16; o > 0; o >>= 1) {
        s  += __shfl_xor_sync(0xffffffffu, s, o);
        ss += __shfl_xor_sync(0xffffffffu, ss, o);
    }
    if (lane == 0) { red[warp4] = s; red[4 + warp4] = ss; }
    asm volatile("bar.sync %0, 128;" :: "r"(barid) : "memory");
    s  = red[0] + red[1] + red[2] + red[3];
    ss = red[4] + red[5] + red[6] + red[7];
}

DEV void group_bar(int barid) {
    asm volatile("bar.sync %0, 128;" :: "r"(barid) : "memory");
}

// permutation of param-gen columns: p1 block (n<16384): (h,c,d) -> (h,d,c)
// involution: permn(permn(n)) == n
DEV int permn(int n) {
    if (n < 16384) {
        int h = n >> 12, rem = n & 4095, c = rem >> 6, d = rem & 63;
        return (h << 12) + (d << 6) + c;
    }
    return n;
}

// ---------------------------------------------------------------------------
// fp16 GEMM mainloop: CTA tile 128x128, BK=32, 4-stage cp.async pipeline.
// 8 warps as 2x4 grid, warp tile 64x32. smem/stage: A 128x80B + B 128x80B.
// ---------------------------------------------------------------------------
DEV void stage_load(uint32_t sbase,
                    const __half* __restrict__ A, int lda, int mBase,
                    const __half* __restrict__ Bt, int ldb, int nBase,
                    int k0, int t) {
#pragma unroll
    for (int j = 0; j < 2; ++j) {
        int i = t + j * 256, r = i >> 2, c = i & 3;
        int gr = mBase + r;
        const __half* sa = A + (size_t)(gr < MROWS ? gr : 0) * lda + k0 + c * 8;
        cp16(sbase + (uint32_t)(r * 80 + c * 16), sa, gr < MROWS ? 16 : 0);
        const __half* sb = Bt + (size_t)(nBase + r) * ldb + k0 + c * 8;
        cp16(sbase + 10240u + (uint32_t)(r * 80 + c * 16), sb, 16);
    }
}

template <int NT>
DEV void mainloop_h(const __half* __restrict__ A, int lda, int mBase,
                    const __half* __restrict__ Bt, int ldb, int nBase,
                    int kStart, uint32_t sm32, float (&acc)[4][4][4], int t) {
    const int lane = t & 31, warp = t >> 5;
    const int wr = warp >> 2, wc = warp & 3;
    const int sub = lane & 7;

    const int aRow = ((lane >> 3) & 1) * 8 + sub;
    const int aK   = (lane >> 4) * 8;
    const int bRow = (lane >> 4) * 8 + sub;
    const int bK   = ((lane >> 3) & 1) * 8;

    // preload 3 stages (NT >= 3 for all users)
    stage_load(sm32, A, lda, mBase, Bt, ldb, nBase, kStart, t);
    cp_commit();
    stage_load(sm32 + STAGE_BYTES, A, lda, mBase, Bt, ldb, nBase, kStart + 32, t);
    cp_commit();
    stage_load(sm32 + 2 * STAGE_BYTES, A, lda, mBase, Bt, ldb, nBase, kStart + 64, t);
    cp_commit();

    for (int kt = 0; kt < NT; ++kt) {
        cp_wait2();            // stage kt complete (<=2 younger groups pending)
        __syncthreads();

        const uint32_t aB = sm32 + (uint32_t)((kt % STAGES) * STAGE_BYTES);
        const uint32_t bB = aB + 10240u;

#pragma unroll
        for (int kk = 0; kk < 32; kk += 16) {
            uint32_t af[4][4], bf[4][2];
#pragma unroll
            for (int mi = 0; mi < 4; ++mi) {
                int r = wr * 64 + mi * 16 + aRow;
                ldsm4(af[mi][0], af[mi][1], af[mi][2], af[mi][3],
                      aB + (uint32_t)(r * 80 + (kk + aK) * 2));
            }
#pragma unroll
            for (int n2 = 0; n2 < 2; ++n2) {
                int n = wc * 32 + n2 * 16 + bRow;
                ldsm4(bf[n2 * 2][0], bf[n2 * 2][1], bf[n2 * 2 + 1][0],
                      bf[n2 * 2 + 1][1],
                      bB + (uint32_t)(n * 80 + (kk + bK) * 2));
            }
#pragma unroll
            for (int mi = 0; mi < 4; ++mi)
#pragma unroll
                for (int ni = 0; ni < 4; ++ni) mma16(acc[mi][ni], af[mi], bf[ni]);
        }

        // prefetch kt+3 into stage (kt+3)%4 (all warps passed this iter's
        // sync, so stage (kt-1)%4 reads are complete)
        if (kt + 3 < NT)
            stage_load(sm32 + (uint32_t)(((kt + 3) % STAGES) * STAGE_BYTES),
                       A, lda, mBase, Bt, ldb, nBase, kStart + (kt + 3) * 32, t);
        cp_commit();
    }
}

// ---------------------------------------------------------------------------
// GEMM1: g_params_h = qf_h @ wgenT_h^T + b_gen[permn(.)]   grid(192,29)
// ---------------------------------------------------------------------------
__global__ void __launch_bounds__(256, 2)
gemm1_h_kernel(const float* __restrict__ b_gen) {
    extern __shared__ __align__(128) __half smem_dyn[];
    const int t = threadIdx.x, lane = t & 31, warp = t >> 5;
    const int g = lane >> 2, tg = lane & 3;
    const int wr = warp >> 2, wc = warp & 3;
    const int mBase = blockIdx.y * 128, nBase = blockIdx.x * 128;

    float acc[4][4][4];
#pragma unroll
    for (int i = 0; i < 4; ++i)
#pragma unroll
        for (int j = 0; j < 4; ++j)
#pragma unroll
            for (int k = 0; k < 4; ++k) acc[i][j][k] = 0.f;

    mainloop_h<8>(g_qf_h, K1, mBase, g_wgenT_h, K1, nBase, 0,
                  smem_u32(smem_dyn), acc, t);

#pragma unroll
    for (int mi = 0; mi < 4; ++mi) {
        int r0 = mBase + wr * 64 + mi * 16 + g;
#pragma unroll
        for (int ni = 0; ni < 4; ++ni) {
            int c0 = nBase + wc * 32 + ni * 8 + tg * 2;
            float b0 = b_gen[permn(c0)], b1 = b_gen[permn(c0 + 1)];
            if (r0 < MROWS)
                *(__half2*)(g_params_h + (size_t)r0 * N1 + c0) =
                    __floats2half2_rn(acc[mi][ni][0] + b0, acc[mi][ni][1] + b1);
            if (r0 + 8 < MROWS)
                *(__half2*)(g_params_h + (size_t)(r0 + 8) * N1 + c0) =
                    __floats2half2_rn(acc[mi][ni][2] + b0, acc[mi][ni][3] + b1);
        }
    }
}

// ---------------------------------------------------------------------------
// GEMM3: g_part[z] = g_mid_h @ woutT_h^T    grid(2,29,16)
// ---------------------------------------------------------------------------
__global__ void __launch_bounds__(256, 2)
gemm3_h_kernel() {
    extern __shared__ __align__(128) __half smem_dyn[];
    const int t = threadIdx.x, lane = t & 31, warp = t >> 5;
    const int g = lane >> 2, tg = lane & 3;
    const int wr = warp >> 2, wc = warp & 3;
    const int mBase = blockIdx.y * 128, nBase = blockIdx.x * 128;
    const int kStart = blockIdx.z * (NMID / SPLITK);

    float acc[4][4][4];
#pragma unroll
    for (int i = 0; i < 4; ++i)
#pragma unroll
        for (int j = 0; j < 4; ++j)
#pragma unroll
            for (int k = 0; k < 4; ++k) acc[i][j][k] = 0.f;

    mainloop_h<(NMID / SPLITK) / 32>(g_mid_h, NMID, mBase, g_woutT_h, NMID,
                                     nBase, kStart, smem_u32(smem_dyn), acc, t);

    float* pbase = g_part + (size_t)blockIdx.z * MROWS * NOUT;
#pragma unroll
    for (int mi = 0; mi < 4; ++mi) {
        int r0 = mBase + wr * 64 + mi * 16 + g;
#pragma unroll
        for (int ni = 0; ni < 4; ++ni) {
            int c0 = nBase + wc * 32 + ni * 8 + tg * 2;
            if (r0 < MROWS) {
                pbase[(size_t)r0 * NOUT + c0]     = acc[mi][ni][0];
                pbase[(size_t)r0 * NOUT + c0 + 1] = acc[mi][ni][1];
            }
            if (r0 + 8 < MROWS) {
                pbase[(size_t)(r0 + 8) * NOUT + c0]     = acc[mi][ni][2];
                pbase[(size_t)(r0 + 8) * NOUT + c0 + 1] = acc[mi][ni][3];
            }
        }
    }
}

// ---------------------------------------------------------------------------
// Mid kernel (fp16 HMMA): one CTA per (b,q) row; two independent 128-thread
// head-groups (warps 0-3: heads 0,2; warps 4-7: heads 1,3), named barriers.
// ---------------------------------------------------------------------------
__global__ void __launch_bounds__(256, 3)
mid_h_kernel(const float* __restrict__ sampled) {
    __shared__ __align__(16) __half sP1[2][64 * 72];  // [d][c]
    __shared__ __align__(16) __half sS[2][32 * 72];   // [p][c]
    __shared__ __align__(16) __half sP2[2][64 * 40];  // [e][p]
    __shared__ __align__(16) __half sO1[2][64 * 40];  // [d][p]
    __shared__ float red[2][8];

    const int row = blockIdx.x, t = threadIdx.x;
    const int lane = t & 31;
    const int wg = t >> 7;            // head-group 0/1
    const int wt = t & 127;           // thread-in-group
    const int warp4 = wt >> 5;        // warp-in-group 0-3
    const int g = lane >> 2, tg = lane & 3;
    const int barid = wg + 1;

    const __half* prow = g_params_h + (size_t)row * N1;
    const float* srow = sampled + (size_t)row * 8192;
    __half* mrow = g_mid_h + (size_t)row * NMID;

    __half* P1 = sP1[wg];
    __half* S  = sS[wg];
    __half* P2 = sP2[wg];
    __half* O1 = sO1[wg];
    float*  rd = red[wg];

    const int mA = (warp4 & 1) * 16;
    const int nA = (warp4 >> 1) * 32;
    const int mB = (warp4 & 1) * 32;
    const int nB = (warp4 >> 1) * 32;

    for (int h2 = 0; h2 < 2; ++h2) {
        const int head = h2 * 2 + wg;
        group_bar(barid);

#pragma unroll
        for (int j = 0; j < 4; ++j) {
            int i = wt + j * 128, d = i >> 3, c8 = i & 7;
            *(uint4*)(P1 + d * 72 + c8 * 8) =
                *(const uint4*)(prow + head * 4096 + d * 64 + c8 * 8);
        }
#pragma unroll
        for (int j = 0; j < 4; ++j) {
            int i = wt + j * 128, p = i >> 4, c4 = i & 15;
            float4 v = *(const float4*)(srow + head * 2048 + p * 64 + c4 * 4);
            __half2 ha = __floats2half2_rn(v.x, v.y);
            __half2 hb = __floats2half2_rn(v.z, v.w);
            *(uint2*)(S + p * 72 + c4 * 4) =
                make_uint2(*(uint32_t*)&ha, *(uint32_t*)&hb);
        }
#pragma unroll
        for (int j = 0; j < 2; ++j) {
            int i = wt + j * 128, e = i >> 2, p8 = i & 3;
            *(uint4*)(P2 + e * 40 + p8 * 8) =
                *(const uint4*)(prow + 16384 + head * 2048 + e * 32 + p8 * 8);
        }
        group_bar(barid);

        // ---- stage A: M=32(p) N=64(d) K=64(c), warp tile 16x32 ----
        float accA[4][4];
#pragma unroll
        for (int i = 0; i < 4; ++i)
#pragma unroll
            for (int j = 0; j < 4; ++j) accA[i][j] = 0.f;

        const int p0 = mA + g;
#pragma unroll
        for (int kk = 0; kk < 64; kk += 16) {
            uint32_t a[4];
            a[0] = *(const uint32_t*)(S + p0 * 72 + kk + 2 * tg);
            a[1] = *(const uint32_t*)(S + (p0 + 8) * 72 + kk + 2 * tg);
            a[2] = *(const uint32_t*)(S + p0 * 72 + kk + 2 * tg + 8);
            a[3] = *(const uint32_t*)(S + (p0 + 8) * 72 + kk + 2 * tg + 8);
#pragma unroll
            for (int ni = 0; ni < 4; ++ni) {
                int nd = nA + ni * 8 + g;
                uint32_t b[2];
                b[0] = *(const uint32_t*)(P1 + nd * 72 + kk + 2 * tg);
                b[1] = *(const uint32_t*)(P1 + nd * 72 + kk + 2 * tg + 8);
                mma16(accA[ni], a, b);
            }
        }

        float s = 0.f, ss = 0.f;
#pragma unroll
        for (int i = 0; i < 4; ++i)
#pragma unroll
            for (int j = 0; j < 4; ++j) {
                accA[i][j] = gelu_exact(accA[i][j]);
                s += accA[i][j]; ss += accA[i][j] * accA[i][j];
            }
        group_reduce2(s, ss, rd, warp4, lane, barid);
        float mean = s * (1.f / 2048.f);
        float inv  = rsqrtf(ss * (1.f / 2048.f) - mean * mean + 1e-5f);
#pragma unroll
        for (int ni = 0; ni < 4; ++ni) {
            int d0 = nA + ni * 8 + 2 * tg;
            O1[d0 * 40 + p0]           = __float2half_rn((accA[ni][0] - mean) * inv);
            O1[(d0 + 1) * 40 + p0]     = __float2half_rn((accA[ni][1] - mean) * inv);
            O1[d0 * 40 + p0 + 8]       = __float2half_rn((accA[ni][2] - mean) * inv);
            O1[(d0 + 1) * 40 + p0 + 8] = __float2half_rn((accA[ni][3] - mean) * inv);
        }
        group_bar(barid);

        // ---- stage B: M=64(e) N=64(d) K=32(p), warp tile 32x32 ----
        float accB[2][4][4];
#pragma unroll
        for (int i = 0; i < 2; ++i)
#pragma unroll
            for (int j = 0; j < 4; ++j)
#pragma unroll
                for (int k = 0; k < 4; ++k) accB[i][j][k] = 0.f;

#pragma unroll
        for (int kk = 0; kk < 32; kk += 16) {
            uint32_t a[2][4];
#pragma unroll
            for (int mi = 0; mi < 2; ++mi) {
                int e0 = mB + mi * 16 + g;
                a[mi][0] = *(const uint32_t*)(P2 + e0 * 40 + kk + 2 * tg);
                a[mi][1] = *(const uint32_t*)(P2 + (e0 + 8) * 40 + kk + 2 * tg);
                a[mi][2] = *(const uint32_t*)(P2 + e0 * 40 + kk + 2 * tg + 8);
                a[mi][3] = *(const uint32_t*)(P2 + (e0 + 8) * 40 + kk + 2 * tg + 8);
            }
#pragma unroll
            for (int ni = 0; ni < 4; ++ni) {
                int nd = nB + ni * 8 + g;
                uint32_t b[2];
                b[0] = *(const uint32_t*)(O1 + nd * 40 + kk + 2 * tg);
                b[1] = *(const uint32_t*)(O1 + nd * 40 + kk + 2 * tg + 8);
#pragma unroll
                for (int mi = 0; mi < 2; ++mi) mma16(accB[mi][ni], a[mi], b);
            }
        }

        s = 0.f; ss = 0.f;
#pragma unroll
        for (int i = 0; i < 2; ++i)
#pragma unroll
            for (int j = 0; j < 4; ++j)
#pragma unroll
                for (int k = 0; k < 4; ++k) {
                    accB[i][j][k] = gelu_exact(accB[i][j][k]);
                    s += accB[i][j][k]; ss += accB[i][j][k] * accB[i][j][k];
                }
        group_reduce2(s, ss, rd, warp4, lane, barid);
        mean = s * (1.f / 4096.f);
        inv  = rsqrtf(ss * (1.f / 4096.f) - mean * mean + 1e-5f);
        __half* hrow = mrow + head * 4096;
#pragma unroll
        for (int mi = 0; mi < 2; ++mi) {
            int e0 = mB + mi * 16 + g;
#pragma unroll
            for (int ni = 0; ni < 4; ++ni) {
                int c0 = nB + ni * 8 + 2 * tg;
                *(__half2*)(hrow + e0 * 64 + c0) =
                    __floats2half2_rn((accB[mi][ni][0] - mean) * inv,
                                      (accB[mi][ni][1] - mean) * inv);
                *(__half2*)(hrow + (e0 + 8) * 64 + c0) =
                    __floats2half2_rn((accB[mi][ni][2] - mean) * inv,
                                      (accB[mi][ni][3] - mean) * inv);
            }
        }
    }
}

// ---------------------------------------------------------------------------
// conversions
// ---------------------------------------------------------------------------
__global__ void __launch_bounds__(256)
cvt_qf_kernel(const float* __restrict__ in) {
    int i = blockIdx.x * 256 + threadIdx.x;
    float4 v = *(const float4*)(in + (size_t)i * 4);
    __half2 ha = __floats2half2_rn(v.x, v.y);
    __half2 hb = __floats2half2_rn(v.z, v.w);
    *(uint2*)(g_qf_h + (size_t)i * 4) = make_uint2(*(uint32_t*)&ha, *(uint32_t*)&hb);
}

__global__ void __launch_bounds__(256)
cvt_wgen_kernel(const float* __restrict__ in) {
    __shared__ float tile[32][33];
    const int n0 = blockIdx.x * 32, k0 = blockIdx.y * 32;
    const int tx = threadIdx.x, ty = threadIdx.y;
#pragma unroll
    for (int j = 0; j < 32; j += 8)
        tile[ty + j][tx] = in[(size_t)(k0 + ty + j) * N1 + n0 + tx];
    __syncthreads();
#pragma unroll
    for (int j = 0; j < 32; j += 8) {
        int np = permn(n0 + ty + j);
        g_wgenT_h[(size_t)np * K1 + k0 + tx] = __float2half_rn(tile[tx][ty + j]);
    }
}

__global__ void __launch_bounds__(256)
cvt_wout_kernel(const float* __restrict__ in) {
    __shared__ float tile[32][33];
    const int n0 = blockIdx.x * 32, k0 = blockIdx.y * 32;
    const int tx = threadIdx.x, ty = threadIdx.y;
#pragma unroll
    for (int j = 0; j < 32; j += 8)
        tile[ty + j][tx] = in[(size_t)(k0 + ty + j) * NOUT + n0 + tx];
    __syncthreads();
#pragma unroll
    for (int j = 0; j < 32; j += 8)
        g_woutT_h[(size_t)(n0 + ty + j) * NMID + k0 + tx] = __float2half_rn(tile[tx][ty + j]);
}

// ---------------------------------------------------------------------------
// Epilogue: deterministic split-K reduce + bias + affine LayerNorm(256)
// ---------------------------------------------------------------------------
__global__ void __launch_bounds__(256, 1)
out_ln_kernel(const float* __restrict__ b_out, const float* __restrict__ ln_w,
              const float* __restrict__ ln_b, float* __restrict__ out) {
    __shared__ float red[16];
    const int row = blockIdx.x, t = threadIdx.x;
    float v = b_out[t];
#pragma unroll
    for (int sp = 0; sp < SPLITK; ++sp)
        v += g_part[(size_t)sp * MROWS * NOUT + (size_t)row * NOUT + t];
    float s = v, ss = v * v;
    block_reduce2(s, ss, red, t);
    float mean = s * (1.f / 256.f);
    float inv  = rsqrtf(ss * (1.f / 256.f) - mean * mean + 1e-5f);
    out[(size_t)row * NOUT + t] = (v - mean) * inv * ln_w[t] + ln_b[t];
}

// ---------------------------------------------------------------------------
extern "C" void kernel_launch(void* const* d_in, const int* in_sizes, int n_in,
                              void* d_out, int out_size) {
    (void)in_sizes; (void)n_in; (void)out_size;
    const float* qf      = (const float*)d_in[0];
    const float* sampled = (const float*)d_in[1];
    const float* W_gen   = (const float*)d_in[2];
    const float* b_gen   = (const float*)d_in[3];
    const float* W_out   = (const float*)d_in[4];
    const float* b_out   = (const float*)d_in[5];
    const float* ln_w    = (const float*)d_in[6];
    const float* ln_b    = (const float*)d_in[7];

    cudaFuncSetAttribute(gemm1_h_kernel,
                         cudaFuncAttributeMaxDynamicSharedMemorySize, SMEM_BYTES);
    cudaFuncSetAttribute(gemm3_h_kernel,
                         cudaFuncAttributeMaxDynamicSharedMemorySize, SMEM_BYTES);

    cvt_qf_kernel<<<(MROWS * K1 / 4) / 256, 256>>>(qf);
    cvt_wgen_kernel<<<dim3(N1 / 32, K1 / 32), dim3(32, 8)>>>(W_gen);
    cvt_wout_kernel<<<dim3(NOUT / 32, NMID / 32), dim3(32, 8)>>>(W_out);

    gemm1_h_kernel<<<dim3(N1 / 128, (MROWS + 127) / 128), 256, SMEM_BYTES>>>(b_gen);
    mid_h_kernel<<<MROWS, 256>>>(sampled);
    gemm3_h_kernel<<<dim3(NOUT / 128, (MROWS + 127) / 128, SPLITK), 256, SMEM_BYTES>>>();
    out_ln_kernel<<<MROWS, 256>>>(b_out, ln_w, ln_b, (float*)d_out);
}